// round 4
// baseline (speedup 1.0000x reference)
#include <cuda_runtime.h>
#include <cuda_bf16.h>

// out[b, j, k] = sum_d x[b, node(j), d] * W[j, d, k] + bias[j, k]
// node(j) = j + 1 (NODE_TO_JOINT = [-1, 0, 1, ..., 11])
// B = 65536, NODES = 13, D = 256, J = 12, K = 2
//
// One warp per (b, j) row. Lane l loads x float4 at element offset l (bytes
// [16l,16l+16)) and l+32 — two perfectly coalesced 512B spans per warp.
// W (12*256*2 floats = 24KB) is L1/L2 resident. Butterfly-reduce 2 accums,
// lane 0 writes float2 + bias.

#define NODES 13
#define DIM   256
#define NJ    12

__global__ void __launch_bounds__(256)
detok_kernel(const float* __restrict__ x,
             const float* __restrict__ W,
             const float* __restrict__ bias,
             float* __restrict__ out,
             int total_rows)   // B * NJ
{
    int gwarp = (blockIdx.x * blockDim.x + threadIdx.x) >> 5;
    int lane  = threadIdx.x & 31;
    if (gwarp >= total_rows) return;

    int b = gwarp / NJ;
    int j = gwarp - b * NJ;
    int node = j + 1;

    const float4* __restrict__ xr =
        reinterpret_cast<const float4*>(x + ((long long)b * NODES + node) * DIM);
    const float4* __restrict__ wr =
        reinterpret_cast<const float4*>(W + j * (DIM * 2));

    // Front-batch all loads (MLP).
    // Lane handles d in {4*lane .. 4*lane+3} and {128+4*lane .. 128+4*lane+3}.
    float4 x0 = xr[lane];
    float4 x1 = xr[lane + 32];
    // W[j, d, k] flattened: element index d*2+k. For d-block 4*lane:
    // floats [8*lane, 8*lane+8) = float4 indices 2*lane, 2*lane+1.
    float4 wa0 = wr[2 * lane];            // {W[d0,0],W[d0,1],W[d1,0],W[d1,1]}
    float4 wa1 = wr[2 * lane + 1];        // {W[d2,0],W[d2,1],W[d3,0],W[d3,1]}
    float4 wb0 = wr[64 + 2 * lane];       // d+128 block
    float4 wb1 = wr[64 + 2 * lane + 1];

    float acc0, acc1;
    acc0  = x0.x * wa0.x;
    acc1  = x0.x * wa0.y;
    acc0 += x0.y * wa0.z;
    acc1 += x0.y * wa0.w;
    acc0 += x0.z * wa1.x;
    acc1 += x0.z * wa1.y;
    acc0 += x0.w * wa1.z;
    acc1 += x0.w * wa1.w;

    acc0 += x1.x * wb0.x;
    acc1 += x1.x * wb0.y;
    acc0 += x1.y * wb0.z;
    acc1 += x1.y * wb0.w;
    acc0 += x1.z * wb1.x;
    acc1 += x1.z * wb1.y;
    acc0 += x1.w * wb1.z;
    acc1 += x1.w * wb1.w;

    // Warp butterfly reduction of both accumulators.
    #pragma unroll
    for (int off = 16; off > 0; off >>= 1) {
        acc0 += __shfl_xor_sync(0xFFFFFFFFu, acc0, off);
        acc1 += __shfl_xor_sync(0xFFFFFFFFu, acc1, off);
    }

    if (lane == 0) {
        float2 bj = reinterpret_cast<const float2*>(bias)[j];
        float2 r;
        r.x = acc0 + bj.x;
        r.y = acc1 + bj.y;
        reinterpret_cast<float2*>(out)[gwarp] = r;
    }
}

extern "C" void kernel_launch(void* const* d_in, const int* in_sizes, int n_in,
                              void* d_out, int out_size)
{
    const float* x    = (const float*)d_in[0];   // (B, 13, 256)
    const float* W    = (const float*)d_in[1];   // (12, 256, 2)
    const float* bias = (const float*)d_in[2];   // (12, 2)
    float* out = (float*)d_out;                  // (B, 12, 2)

    int B = in_sizes[0] / (NODES * DIM);
    int total_rows = B * NJ;

    const int threads = 256;                 // 8 warps per CTA
    int warps_per_block = threads / 32;
    int blocks = (total_rows + warps_per_block - 1) / warps_per_block;

    detok_kernel<<<blocks, threads>>>(x, W, bias, out, total_rows);
}

// round 5
// speedup vs baseline: 1.2021x; 1.2021x over previous
#include <cuda_runtime.h>
#include <cuda_bf16.h>

// out[b, j, k] = sum_d x[b, j+1, d] * W[j, d, k] + bias[j, k]
// B = 65536, NODES = 13, D = 256, J = 12, K = 2
//
// One warp per (j, 4 batch rows). W registers (4 x float4) amortized over 4
// rows -> L1 wavefronts per output row halved vs warp-per-row. 8 x-loads
// front-batched for MLP. x loads use __ldcs (pure streaming).

#define NODES 13
#define DIM   256
#define NJ    12
#define RB    4     // batch rows per warp

__global__ void __launch_bounds__(256)
detok_kernel(const float* __restrict__ x,
             const float* __restrict__ W,
             const float* __restrict__ bias,
             float* __restrict__ out,
             int num_groups)   // (B/RB) * NJ
{
    int gwarp = (blockIdx.x * blockDim.x + threadIdx.x) >> 5;
    int lane  = threadIdx.x & 31;
    if (gwarp >= num_groups) return;

    int bg = gwarp / NJ;
    int j  = gwarp - bg * NJ;
    int b0 = bg * RB;
    int node = j + 1;

    // W[j] : 256x2 floats = 2KB. Lane l covers d in {4l..4l+3} and {128+4l..}.
    const float4* __restrict__ wr =
        reinterpret_cast<const float4*>(W + j * (DIM * 2));
    float4 wa0 = wr[2 * lane];
    float4 wa1 = wr[2 * lane + 1];
    float4 wb0 = wr[64 + 2 * lane];
    float4 wb1 = wr[64 + 2 * lane + 1];

    // Front-batch all x loads (8 outstanding LDG.128 per lane).
    float4 x0[RB], x1[RB];
#pragma unroll
    for (int r = 0; r < RB; r++) {
        const float4* __restrict__ xr = reinterpret_cast<const float4*>(
            x + ((long long)(b0 + r) * NODES + node) * DIM);
        x0[r] = __ldcs(xr + lane);
        x1[r] = __ldcs(xr + lane + 32);
    }

    float a0[RB], a1[RB];
#pragma unroll
    for (int r = 0; r < RB; r++) {
        a0[r] = x0[r].x * wa0.x + x0[r].y * wa0.z
              + x0[r].z * wa1.x + x0[r].w * wa1.z
              + x1[r].x * wb0.x + x1[r].y * wb0.z
              + x1[r].z * wb1.x + x1[r].w * wb1.z;
        a1[r] = x0[r].x * wa0.y + x0[r].y * wa0.w
              + x0[r].z * wa1.y + x0[r].w * wa1.w
              + x1[r].x * wb0.y + x1[r].y * wb0.w
              + x1[r].z * wb1.y + x1[r].w * wb1.w;
    }

    // Butterfly-reduce all 8 accumulators across the warp.
#pragma unroll
    for (int off = 16; off > 0; off >>= 1) {
#pragma unroll
        for (int r = 0; r < RB; r++) {
            a0[r] += __shfl_xor_sync(0xFFFFFFFFu, a0[r], off);
            a1[r] += __shfl_xor_sync(0xFFFFFFFFu, a1[r], off);
        }
    }

    if (lane == 0) {
        float2 bj = reinterpret_cast<const float2*>(bias)[j];
#pragma unroll
        for (int r = 0; r < RB; r++) {
            float2 v;
            v.x = a0[r] + bj.x;
            v.y = a1[r] + bj.y;
            reinterpret_cast<float2*>(out)[(b0 + r) * NJ + j] = v;
        }
    }
}

extern "C" void kernel_launch(void* const* d_in, const int* in_sizes, int n_in,
                              void* d_out, int out_size)
{
    const float* x    = (const float*)d_in[0];   // (B, 13, 256)
    const float* W    = (const float*)d_in[1];   // (12, 256, 2)
    const float* bias = (const float*)d_in[2];   // (12, 2)
    float* out = (float*)d_out;                  // (B, 12, 2)

    int B = in_sizes[0] / (NODES * DIM);
    int num_groups = (B / RB) * NJ;              // B = 65536 divisible by 4

    const int threads = 256;                     // 8 warps per CTA
    int warps_per_block = threads / 32;
    int blocks = (num_groups + warps_per_block - 1) / warps_per_block;

    detok_kernel<<<blocks, threads>>>(x, W, bias, out, num_groups);
}